// round 13
// baseline (speedup 1.0000x reference)
#include <cuda_runtime.h>
#include <cuda.h>
#include <stdint.h>

// StationSelectionAggregator:
//   schedule: [B, WIN, N_ST]  one-hot float32
//   csi:      [B, N_ST, N_SUB, WIN] float32
//   out:      [B, WIN, N_SUB] float32
//   out[b,w,s] = csi[b, t(b,w), s, w]  (exact selection; schedule one-hot).
//
// R13: scaling law found — achieved HBM tracks per-SM TMA context count
// (6 ctx: 6.89 TB/s, 8 ctx: 6.97 TB/s). This round: 128-thread CTAs with
// 8 KB boxes -> 16 CTAs/SM = 16 in-flight TMA boxes (2x R12), identical
// per-box DRAM stream. All smem phases re-verified conflict-free.
#define B_    32
#define NST   8
#define NSUB  256
#define WIN   2048

__device__ __forceinline__ uint32_t smem_u32(const void* p) {
    uint32_t a;
    asm("{ .reg .u64 t; cvta.to.shared.u64 t, %1; cvt.u32.u64 %0, t; }"
        : "=r"(a) : "l"(p));
    return a;
}

__device__ __forceinline__ void mbar_wait0(uint32_t mb) {
    uint32_t done;
    asm volatile("{\n\t.reg .pred p;\n\t"
                 "mbarrier.try_wait.parity.acquire.cta.shared::cta.b64 p, [%1], %2;\n\t"
                 "selp.b32 %0, 1, 0, p;\n\t}"
                 : "=r"(done) : "r"(mb), "r"(0u) : "memory");
    if (!done) {
        asm volatile("{\n\t.reg .pred P1;\n\t"
                     "WL_%=:\n\t"
                     "mbarrier.try_wait.parity.acquire.cta.shared::cta.b64 P1, [%0], %1, 0x989680;\n\t"
                     "@P1 bra.uni WD_%=;\n\t"
                     "bra.uni WL_%=;\n\t"
                     "WD_%=:\n\t}"
                     :: "r"(mb), "r"(0u) : "memory");
    }
}

// ---------------- one-shot TMA kernel, 8 KB box, 128 threads ----------------
__global__ __launch_bounds__(128)
void station_select_tma_kernel(const __grid_constant__ CUtensorMap tmap,
                               const float* __restrict__ sched,
                               float* __restrict__ out) {
    // blockIdx.x : w tile (64, fastest), .y : s tile (32), .z : batch (32)
    __shared__ __align__(128) float stage[NST][8][32];   // 8 KB TMA dest
    __shared__ float tile[8][36];                        // stride 36: conflict-free both phases
    __shared__ int   tw[32];
    __shared__ __align__(8) uint64_t mbar;

    const int b   = blockIdx.z;
    const int w0  = blockIdx.x * 32;
    const int s0  = blockIdx.y * 8;
    const int tid = threadIdx.x;     // 0..127
    const int tx  = tid & 31;
    const int ty  = tid >> 5;        // 0..3

    const uint32_t mb = smem_u32(&mbar);

    if (tid == 0) {
        asm volatile("mbarrier.init.shared.b64 [%0], %1;"
                     :: "r"(mb), "r"(1) : "memory");
        asm volatile("mbarrier.arrive.expect_tx.shared.b64 _, [%0], %1;"
                     :: "r"(mb), "r"((uint32_t)(NST * 8 * 32 * 4)) : "memory");
        asm volatile("cp.async.bulk.tensor.3d.shared::cta.global.tile.mbarrier::complete_tx::bytes "
                     "[%0], [%1, {%2, %3, %4}], [%5];"
                     :: "r"(smem_u32(stage)), "l"(&tmap),
                        "r"(w0), "r"(s0), "r"(b * NST), "r"(mb)
                     : "memory");
    }
    // station decode overlaps the TMA fill (exact: one-hot values are 0.0/1.0)
    if (tid < 32) {
        const float4* sp = reinterpret_cast<const float4*>(
            sched + ((size_t)b * WIN + (size_t)(w0 + tid)) * NST);
        const float4 a = sp[0];
        const float4 c = sp[1];
        const float tf = a.y + 2.f * a.z + 3.f * a.w +
                         4.f * c.x + 5.f * c.y + 6.f * c.z + 7.f * c.w;
        tw[tid] = (int)(tf + 0.5f);
    }
    __syncthreads();   // publishes mbar init + tw

    mbar_wait0(mb);

    // smem select: addr%128 == 4*tx -> conflict-free for any plane t
    const int t = tw[tx];
    const float v0 = stage[t][ty][tx];        // s rows ty and ty+4
    const float v1 = stage[t][ty + 4][tx];

    // transpose tile (stride 36): write banks (4*sl + tx)&31, lanes vary tx -> clean
    tile[ty][tx]     = v0;
    tile[ty + 4][tx] = v1;
    __syncthreads();

    // stores: lane -> (sl = tx&7, wr = tx>>3); two w-rows per lane.
    // read banks (4*sl + wl)&31 = 4*(tx&7) + (tx>>3) + const -> 32 distinct.
    const int sl = tx & 7;
    const int wr = tx >> 3;          // 0..3
#pragma unroll
    for (int rr = 0; rr < 2; rr++) {
        const int wl = 8 * ty + 4 * rr + wr;   // 0..31
        out[((size_t)b * WIN + (size_t)(w0 + wl)) * NSUB + (size_t)(s0 + sl)]
            = tile[sl][wl];
    }
}

// ---------------- fallback: R1 LDG kernel ----------------
__global__ __launch_bounds__(256)
void station_select_ldg_kernel(const float* __restrict__ sched,
                               const float* __restrict__ csi,
                               float* __restrict__ out) {
    __shared__ float tile[32][33];
    __shared__ int   tw[32];

    const int b   = blockIdx.z;
    const int w0  = blockIdx.x * 32;
    const int s0  = blockIdx.y * 32;
    const int tid = threadIdx.x;
    const int tx  = tid & 31;
    const int ty  = tid >> 5;

    if (tid < 32) {
        const float4* sp = reinterpret_cast<const float4*>(
            sched + ((size_t)b * WIN + (size_t)(w0 + tid)) * NST);
        const float4 a = sp[0];
        const float4 c = sp[1];
        const float tf = a.y + 2.f * a.z + 3.f * a.w +
                         4.f * c.x + 5.f * c.y + 6.f * c.z + 7.f * c.w;
        tw[tid] = (int)(tf + 0.5f);
    }
    __syncthreads();

    const int t = tw[tx];
    const float* p = csi + ((size_t)(b * NST + t) * NSUB + (size_t)s0) * WIN
                         + (size_t)(w0 + tx);
    float v[4];
#pragma unroll
    for (int r = 0; r < 4; r++)
        v[r] = p[(size_t)(ty + r * 8) * WIN];
#pragma unroll
    for (int r = 0; r < 4; r++)
        tile[ty + r * 8][tx] = v[r];
    __syncthreads();

#pragma unroll
    for (int r = 0; r < 4; r++) {
        const int wl = ty + r * 8;
        out[((size_t)b * WIN + (size_t)(w0 + wl)) * NSUB + (size_t)(s0 + tx)]
            = tile[tx][wl];
    }
}

// ---------------- host ----------------
typedef CUresult (*tmap_encode_fn)(
    CUtensorMap*, CUtensorMapDataType, cuuint32_t, void*,
    const cuuint64_t*, const cuuint64_t*, const cuuint32_t*, const cuuint32_t*,
    CUtensorMapInterleave, CUtensorMapSwizzle, CUtensorMapL2promotion,
    CUtensorMapFloatOOBfill);

extern "C" void kernel_launch(void* const* d_in, const int* in_sizes, int n_in,
                              void* d_out, int out_size) {
    const float* sched = (const float*)d_in[0];
    const float* csi   = (const float*)d_in[1];
    if (n_in >= 2 && in_sizes[0] != 524288) {   // schedule = 32*2048*8 elems
        sched = (const float*)d_in[1];
        csi   = (const float*)d_in[0];
    }
    float* out = (float*)d_out;

    // tensormap: csi viewed as [w=2048][s=256][plane=256(=b*8+t)]
    void* fn = nullptr;
    cudaDriverEntryPointQueryResult qr = cudaDriverEntryPointSymbolNotFound;
#if CUDART_VERSION >= 12050
    cudaGetDriverEntryPointByVersion("cuTensorMapEncodeTiled", &fn, 12000,
                                     cudaEnableDefault, &qr);
#else
    cudaGetDriverEntryPoint("cuTensorMapEncodeTiled", &fn,
                            cudaEnableDefault, &qr);
#endif
    bool ok = false;
    CUtensorMap tmap;
    if (fn != nullptr && qr == cudaDriverEntryPointSuccess) {
        cuuint64_t dims[3]    = {WIN, NSUB, (cuuint64_t)B_ * NST};
        cuuint64_t strides[2] = {(cuuint64_t)WIN * 4,
                                 (cuuint64_t)WIN * NSUB * 4};
        cuuint32_t box[3]     = {32, 8, NST};
        cuuint32_t es[3]      = {1, 1, 1};
        ok = ((tmap_encode_fn)fn)(&tmap, CU_TENSOR_MAP_DATA_TYPE_FLOAT32, 3,
                                  (void*)csi, dims, strides, box, es,
                                  CU_TENSOR_MAP_INTERLEAVE_NONE,
                                  CU_TENSOR_MAP_SWIZZLE_NONE,
                                  CU_TENSOR_MAP_L2_PROMOTION_L2_128B,
                                  CU_TENSOR_MAP_FLOAT_OOB_FILL_NONE)
             == CUDA_SUCCESS;
    }

    if (ok) {
        dim3 grid(WIN / 32, NSUB / 8, B_);
        station_select_tma_kernel<<<grid, 128>>>(tmap, sched, out);
    } else {
        dim3 grid(WIN / 32, NSUB / 32, B_);
        station_select_ldg_kernel<<<grid, 256>>>(sched, csi, out);
    }
}

// round 14
// speedup vs baseline: 1.0051x; 1.0051x over previous
#include <cuda_runtime.h>
#include <cuda.h>
#include <stdint.h>

// StationSelectionAggregator:
//   schedule: [B, WIN, N_ST]  one-hot float32
//   csi:      [B, N_ST, N_SUB, WIN] float32
//   out:      [B, WIN, N_SUB] float32
//   out[b,w,s] = csi[b, t(b,w), s, w]  (exact selection; schedule one-hot).
//
// R14: context count is saturated (8 ctx == 16 ctx == ~6.96 TB/s). New
// variable: TMA box inner run length. box [64 w][8 s][8 t] doubles each
// sequential DRAM run to 256B (was 128B) before the 1KB/2MB hops, plus
// L2_PROMOTION_256B. Grid halves (fewer waves, less per-CTA overhead).
// 256 threads -> 8 CTAs/SM (R12's proven config), 128KB in flight per SM.
#define B_    32
#define NST   8
#define NSUB  256
#define WIN   2048

__device__ __forceinline__ uint32_t smem_u32(const void* p) {
    uint32_t a;
    asm("{ .reg .u64 t; cvta.to.shared.u64 t, %1; cvt.u32.u64 %0, t; }"
        : "=r"(a) : "l"(p));
    return a;
}

__device__ __forceinline__ void mbar_wait0(uint32_t mb) {
    uint32_t done;
    asm volatile("{\n\t.reg .pred p;\n\t"
                 "mbarrier.try_wait.parity.acquire.cta.shared::cta.b64 p, [%1], %2;\n\t"
                 "selp.b32 %0, 1, 0, p;\n\t}"
                 : "=r"(done) : "r"(mb), "r"(0u) : "memory");
    if (!done) {
        asm volatile("{\n\t.reg .pred P1;\n\t"
                     "WL_%=:\n\t"
                     "mbarrier.try_wait.parity.acquire.cta.shared::cta.b64 P1, [%0], %1, 0x989680;\n\t"
                     "@P1 bra.uni WD_%=;\n\t"
                     "bra.uni WL_%=;\n\t"
                     "WD_%=:\n\t}"
                     :: "r"(mb), "r"(0u) : "memory");
    }
}

// -------- one-shot TMA kernel, box [64w][8s][8t] = 16 KB, 256 threads --------
__global__ __launch_bounds__(256)
void station_select_tma_kernel(const __grid_constant__ CUtensorMap tmap,
                               const float* __restrict__ sched,
                               float* __restrict__ out) {
    // blockIdx.x : w tile (32, fastest), .y : s tile (32), .z : batch (32)
    __shared__ __align__(128) float stage[NST][8][64];   // 16 KB TMA dest
    __shared__ float tile[8][68];                        // stride 68: conflict-free both phases
    __shared__ int   tw[64];
    __shared__ __align__(8) uint64_t mbar;

    const int b   = blockIdx.z;
    const int w0  = blockIdx.x * 64;
    const int s0  = blockIdx.y * 8;
    const int tid = threadIdx.x;     // 0..255
    const int tx  = tid & 31;
    const int ty  = tid >> 5;        // 0..7

    const uint32_t mb = smem_u32(&mbar);

    if (tid == 0) {
        asm volatile("mbarrier.init.shared.b64 [%0], %1;"
                     :: "r"(mb), "r"(1) : "memory");
        asm volatile("mbarrier.arrive.expect_tx.shared.b64 _, [%0], %1;"
                     :: "r"(mb), "r"((uint32_t)(NST * 8 * 64 * 4)) : "memory");
        asm volatile("cp.async.bulk.tensor.3d.shared::cta.global.tile.mbarrier::complete_tx::bytes "
                     "[%0], [%1, {%2, %3, %4}], [%5];"
                     :: "r"(smem_u32(stage)), "l"(&tmap),
                        "r"(w0), "r"(s0), "r"(b * NST), "r"(mb)
                     : "memory");
    }
    // station decode overlaps the TMA fill (exact: one-hot values are 0.0/1.0)
    if (tid < 64) {
        const float4* sp = reinterpret_cast<const float4*>(
            sched + ((size_t)b * WIN + (size_t)(w0 + tid)) * NST);
        const float4 a = sp[0];
        const float4 c = sp[1];
        const float tf = a.y + 2.f * a.z + 3.f * a.w +
                         4.f * c.x + 5.f * c.y + 6.f * c.z + 7.f * c.w;
        tw[tid] = (int)(tf + 0.5f);
    }
    __syncthreads();   // publishes mbar init + tw

    mbar_wait0(mb);

    // select: thread -> (w_l = tid&63, sh = tid>>6); banks = w_l&31 -> clean
    const int w_l = tid & 63;
    const int sh  = tid >> 6;        // 0..3, covers s rows sh and sh+4
    const int t   = tw[w_l];
    const float v0 = stage[t][sh][w_l];
    const float v1 = stage[t][sh + 4][w_l];

    // transpose tile (stride 68): write banks (4*s + w_l)&31, w_l spans 32
    // consecutive within a warp -> distinct
    tile[sh][w_l]     = v0;
    tile[sh + 4][w_l] = v1;
    __syncthreads();

    // stores: lane -> (sl = tx&7, wr = tx>>3); warp covers 4 w-rows x 8 s.
    // read banks (4*sl + wl)&31 = 4*(tx&7) + (tx>>3) + const -> 32 distinct.
    const int sl = tx & 7;
    const int wr = tx >> 3;          // 0..3
#pragma unroll
    for (int rr = 0; rr < 2; rr++) {
        const int wl = ty * 8 + rr * 4 + wr;   // 0..63
        out[((size_t)b * WIN + (size_t)(w0 + wl)) * NSUB + (size_t)(s0 + sl)]
            = tile[sl][wl];
    }
}

// ---------------- fallback: R1 LDG kernel ----------------
__global__ __launch_bounds__(256)
void station_select_ldg_kernel(const float* __restrict__ sched,
                               const float* __restrict__ csi,
                               float* __restrict__ out) {
    __shared__ float tile[32][33];
    __shared__ int   tw[32];

    const int b   = blockIdx.z;
    const int w0  = blockIdx.x * 32;
    const int s0  = blockIdx.y * 32;
    const int tid = threadIdx.x;
    const int tx  = tid & 31;
    const int ty  = tid >> 5;

    if (tid < 32) {
        const float4* sp = reinterpret_cast<const float4*>(
            sched + ((size_t)b * WIN + (size_t)(w0 + tid)) * NST);
        const float4 a = sp[0];
        const float4 c = sp[1];
        const float tf = a.y + 2.f * a.z + 3.f * a.w +
                         4.f * c.x + 5.f * c.y + 6.f * c.z + 7.f * c.w;
        tw[tid] = (int)(tf + 0.5f);
    }
    __syncthreads();

    const int t = tw[tx];
    const float* p = csi + ((size_t)(b * NST + t) * NSUB + (size_t)s0) * WIN
                         + (size_t)(w0 + tx);
    float v[4];
#pragma unroll
    for (int r = 0; r < 4; r++)
        v[r] = p[(size_t)(ty + r * 8) * WIN];
#pragma unroll
    for (int r = 0; r < 4; r++)
        tile[ty + r * 8][tx] = v[r];
    __syncthreads();

#pragma unroll
    for (int r = 0; r < 4; r++) {
        const int wl = ty + r * 8;
        out[((size_t)b * WIN + (size_t)(w0 + wl)) * NSUB + (size_t)(s0 + tx)]
            = tile[tx][wl];
    }
}

// ---------------- host ----------------
typedef CUresult (*tmap_encode_fn)(
    CUtensorMap*, CUtensorMapDataType, cuuint32_t, void*,
    const cuuint64_t*, const cuuint64_t*, const cuuint32_t*, const cuuint32_t*,
    CUtensorMapInterleave, CUtensorMapSwizzle, CUtensorMapL2promotion,
    CUtensorMapFloatOOBfill);

extern "C" void kernel_launch(void* const* d_in, const int* in_sizes, int n_in,
                              void* d_out, int out_size) {
    const float* sched = (const float*)d_in[0];
    const float* csi   = (const float*)d_in[1];
    if (n_in >= 2 && in_sizes[0] != 524288) {   // schedule = 32*2048*8 elems
        sched = (const float*)d_in[1];
        csi   = (const float*)d_in[0];
    }
    float* out = (float*)d_out;

    // tensormap: csi viewed as [w=2048][s=256][plane=256(=b*8+t)]
    void* fn = nullptr;
    cudaDriverEntryPointQueryResult qr = cudaDriverEntryPointSymbolNotFound;
#if CUDART_VERSION >= 12050
    cudaGetDriverEntryPointByVersion("cuTensorMapEncodeTiled", &fn, 12000,
                                     cudaEnableDefault, &qr);
#else
    cudaGetDriverEntryPoint("cuTensorMapEncodeTiled", &fn,
                            cudaEnableDefault, &qr);
#endif
    bool ok = false;
    CUtensorMap tmap;
    if (fn != nullptr && qr == cudaDriverEntryPointSuccess) {
        cuuint64_t dims[3]    = {WIN, NSUB, (cuuint64_t)B_ * NST};
        cuuint64_t strides[2] = {(cuuint64_t)WIN * 4,
                                 (cuuint64_t)WIN * NSUB * 4};
        cuuint32_t box[3]     = {64, 8, NST};
        cuuint32_t es[3]      = {1, 1, 1};
        ok = ((tmap_encode_fn)fn)(&tmap, CU_TENSOR_MAP_DATA_TYPE_FLOAT32, 3,
                                  (void*)csi, dims, strides, box, es,
                                  CU_TENSOR_MAP_INTERLEAVE_NONE,
                                  CU_TENSOR_MAP_SWIZZLE_NONE,
                                  CU_TENSOR_MAP_L2_PROMOTION_L2_256B,
                                  CU_TENSOR_MAP_FLOAT_OOB_FILL_NONE)
             == CUDA_SUCCESS;
    }

    if (ok) {
        dim3 grid(WIN / 64, NSUB / 8, B_);
        station_select_tma_kernel<<<grid, 256>>>(tmap, sched, out);
    } else {
        dim3 grid(WIN / 32, NSUB / 32, B_);
        station_select_ldg_kernel<<<grid, 256>>>(sched, csi, out);
    }
}